// round 13
// baseline (speedup 1.0000x reference)
#include <cuda_runtime.h>
#include <cuda_fp16.h>
#include <math.h>
#include <stdint.h>

#define N_NODES 20000
#define H 256
#define R_RBF 64
#define E_EDGES 320000

// ---------------- scratch (device globals; no allocation at launch) ----------
__device__ __half g_xnorm_h[(size_t)N_NODES * H];
__device__ __half g_qkv_h[(size_t)N_NODES * 768];      // [n][q|k|v] fp16
__device__ float  g_agg[(size_t)N_NODES * H];
__device__ __half g_agg_h[(size_t)N_NODES * H];
__device__ __half g_ea_h[(size_t)E_EDGES * R_RBF];
__device__ __half g_wqkv_h[768 * H];
__device__ __half g_wo_h[H * H];
__device__ __half g_wdk_h[H * R_RBF];
__device__ __half g_wdv_h[H * R_RBF];
__device__ float  g_bqkv[768];
__device__ float  g_attn4[(size_t)4 * E_EDGES];        // per-colslice partials
__device__ float  g_s[E_EDGES];
__device__ int    g_src[E_EDGES];
__device__ int    g_dst[E_EDGES];
__device__ int    g_is64;

// ---------------- asm helpers -------------------------------------------------
__device__ __forceinline__ float silu(float t)
{
    return t / (1.f + __expf(-t));
}
__device__ __forceinline__ void mma_f16(float* d, uint32_t a0, uint32_t a1,
                                        uint32_t a2, uint32_t a3,
                                        uint32_t b0, uint32_t b1)
{
    asm volatile(
        "mma.sync.aligned.m16n8k16.row.col.f32.f16.f16.f32 "
        "{%0,%1,%2,%3},{%4,%5,%6,%7},{%8,%9},{%0,%1,%2,%3};"
        : "+f"(d[0]), "+f"(d[1]), "+f"(d[2]), "+f"(d[3])
        : "r"(a0), "r"(a1), "r"(a2), "r"(a3), "r"(b0), "r"(b1));
}
__device__ __forceinline__ void ldsm_x4(uint32_t& r0, uint32_t& r1,
                                        uint32_t& r2, uint32_t& r3, uint32_t a)
{
    asm volatile("ldmatrix.sync.aligned.m8n8.x4.shared.b16 {%0,%1,%2,%3}, [%4];"
                 : "=r"(r0), "=r"(r1), "=r"(r2), "=r"(r3) : "r"(a));
}
__device__ __forceinline__ void ldsm_x2(uint32_t& r0, uint32_t& r1, uint32_t a)
{
    asm volatile("ldmatrix.sync.aligned.m8n8.x2.shared.b16 {%0,%1}, [%2];"
                 : "=r"(r0), "=r"(r1) : "r"(a));
}
__device__ __forceinline__ void cp16(uint32_t dst, const void* src)
{
    asm volatile("cp.async.cg.shared.global [%0], [%1], 16;"
                 :: "r"(dst), "l"(src) : "memory");
}
__device__ __forceinline__ void cp16p(uint32_t dst, const void* src, uint32_t nbytes)
{
    asm volatile("cp.async.cg.shared.global [%0], [%1], 16, %2;"
                 :: "r"(dst), "l"(src), "r"(nbytes) : "memory");
}
__device__ __forceinline__ void cp_commit()
{
    asm volatile("cp.async.commit_group;" ::: "memory");
}
template<int NN>
__device__ __forceinline__ void cp_wait()
{
    asm volatile("cp.async.wait_group %0;" :: "n"(NN) : "memory");
}

// ---------------- edge_index dtype detection ---------------------------------
__global__ void detect_idx_kernel(const int* __restrict__ p)
{
    if (threadIdx.x == 0 && blockIdx.x == 0) {
        int all_zero = 1;
        for (int i = 0; i < 64; i++)
            if (p[2 * i + 1] != 0) { all_zero = 0; break; }
        g_is64 = all_zero;
    }
}

// ---------------- edge_attr fp32->fp16 + index conversion (fused) ------------
__global__ void conv_ea_kernel(const float* __restrict__ ea,
                               const void* __restrict__ p)
{
    int t = blockIdx.x * blockDim.x + threadIdx.x;
    size_t i = (size_t)t * 8;
    if (i < (size_t)E_EDGES * R_RBF) {
        float4 f0 = *(const float4*)&ea[i];
        float4 f1 = *(const float4*)&ea[i + 4];
        __half2* o = (__half2*)&g_ea_h[i];
        o[0] = __floats2half2_rn(f0.x, f0.y);
        o[1] = __floats2half2_rn(f0.z, f0.w);
        o[2] = __floats2half2_rn(f1.x, f1.y);
        o[3] = __floats2half2_rn(f1.z, f1.w);
    }
    if (t < E_EDGES) {
        if (g_is64) {
            const long long* q = (const long long*)p;
            g_src[t] = (int)q[t];
            g_dst[t] = (int)q[E_EDGES + t];
        } else {
            const int* q = (const int*)p;
            g_src[t] = q[t];
            g_dst[t] = q[E_EDGES + t];
        }
    }
}

__global__ void conv_w_kernel(const float* __restrict__ Wq, const float* __restrict__ Wk,
                              const float* __restrict__ Wv, const float* __restrict__ Wo,
                              const float* __restrict__ Wdk, const float* __restrict__ Wdv,
                              const float* __restrict__ bq, const float* __restrict__ bk,
                              const float* __restrict__ bv)
{
    int i = blockIdx.x * blockDim.x + threadIdx.x;   // 0..196607
    {   // wqkv pack
        int n = i >> 8, c = i & 255;
        float w = (n < 256) ? Wq[n * 256 + c]
                : (n < 512) ? Wk[(n - 256) * 256 + c]
                            : Wv[(n - 512) * 256 + c];
        g_wqkv_h[i] = __float2half_rn(w);
    }
    if (i < 65536) g_wo_h[i]  = __float2half_rn(Wo[i]);
    if (i < 16384) g_wdk_h[i] = __float2half_rn(Wdk[i]);
    if (i < 16384) g_wdv_h[i] = __float2half_rn(Wdv[i]);
    if (i < 768)
        g_bqkv[i] = (i < 256) ? bq[i] : (i < 512) ? bk[i - 256] : bv[i - 512];
}

__global__ void conv_agg_kernel()
{
    size_t i = ((size_t)blockIdx.x * blockDim.x + threadIdx.x) * 8;
    if (i >= (size_t)N_NODES * H) return;
    float4 f0 = *(const float4*)&g_agg[i];
    float4 f1 = *(const float4*)&g_agg[i + 4];
    __half2* o = (__half2*)&g_agg_h[i];
    o[0] = __floats2half2_rn(f0.x, f0.y);
    o[1] = __floats2half2_rn(f0.z, f0.w);
    o[2] = __floats2half2_rn(f1.x, f1.y);
    o[3] = __floats2half2_rn(f1.z, f1.w);
}

// ---------------- LayerNorm: warp per node (fp32 in -> half out, zero agg) ---
__global__ void ln_kernel(const float* __restrict__ x,
                          const float* __restrict__ g,
                          const float* __restrict__ b)
{
    int warp = threadIdx.x >> 5;
    int lane = threadIdx.x & 31;
    int n = blockIdx.x * 8 + warp;
    const float4* xr = (const float4*)(x + (size_t)n * H);
    float4 a0 = xr[lane * 2];
    float4 a1 = xr[lane * 2 + 1];
    float s1 = a0.x + a0.y + a0.z + a0.w + a1.x + a1.y + a1.z + a1.w;
    float s2 = a0.x*a0.x + a0.y*a0.y + a0.z*a0.z + a0.w*a0.w
             + a1.x*a1.x + a1.y*a1.y + a1.z*a1.z + a1.w*a1.w;
    #pragma unroll
    for (int o = 16; o; o >>= 1) {
        s1 += __shfl_xor_sync(0xffffffffu, s1, o);
        s2 += __shfl_xor_sync(0xffffffffu, s2, o);
    }
    float mu  = s1 * (1.0f / H);
    float var = s2 * (1.0f / H) - mu * mu;
    float rs  = rsqrtf(var + 1e-5f);

    float4 g0 = ((const float4*)g)[lane * 2];
    float4 g1 = ((const float4*)g)[lane * 2 + 1];
    float4 b0 = ((const float4*)b)[lane * 2];
    float4 b1 = ((const float4*)b)[lane * 2 + 1];

    __half2 h[4];
    h[0] = __floats2half2_rn((a0.x - mu) * rs * g0.x + b0.x,
                             (a0.y - mu) * rs * g0.y + b0.y);
    h[1] = __floats2half2_rn((a0.z - mu) * rs * g0.z + b0.z,
                             (a0.w - mu) * rs * g0.w + b0.w);
    h[2] = __floats2half2_rn((a1.x - mu) * rs * g1.x + b1.x,
                             (a1.y - mu) * rs * g1.y + b1.y);
    h[3] = __floats2half2_rn((a1.z - mu) * rs * g1.z + b1.z,
                             (a1.w - mu) * rs * g1.w + b1.w);
    *(uint4*)(g_xnorm_h + (size_t)n * H + lane * 8) = *(uint4*)h;

    float4 z = make_float4(0.f, 0.f, 0.f, 0.f);
    float4* ar = (float4*)(g_agg + (size_t)n * H);
    ar[lane * 2]     = z;
    ar[lane * 2 + 1] = z;
}

// ---------------- fp16 tensor-core GEMM: C = A[M,K] @ W[Nout,K]^T ------------
// Block 128x64, 8 warps (2m x 4n), warp tile 64x16, mma m16n8k16.
// STAGES=1 when KTILES==1 (24KB smem).
// EPI 0: half C = acc + bias      (C = g_qkv_h packed, ldc=768 halfs)
// EPI 2: float C = acc + bias + residual
// EPI 3: attn partial -> g_attn4[blockIdx.y*E + e]  (staged, sector-gathers)
// EPI 4: red.add.v4(agg[dst], silu(acc+b)*s[e]*v[src]) (staged, sector-gathers)
template<int EPI, int KTILES>
__global__ void __launch_bounds__(256)
gemm_h(const __half* __restrict__ A, int M, int ldA,
       const __half* __restrict__ W, int ldW,
       const float* __restrict__ bias,
       void* __restrict__ Cv, int ldc,
       const float* __restrict__ residual)
{
    constexpr int STAGES = (KTILES > 1) ? 2 : 1;
    __shared__ __align__(16) char sbuf[STAGES * (16384 + 8192)];
    // mainloop views
    uint32_t aBase = (uint32_t)__cvta_generic_to_shared(sbuf);
    uint32_t wBase = aBase + STAGES * 16384;
    // epilogue staging view (fp32 [64][68], 17408B <= 24KB)
    float* stg = (float*)sbuf;

    int tid  = threadIdx.x;
    int lane = tid & 31;
    int w    = tid >> 5;
    int wm   = (w & 1) * 64;
    int wn   = (w >> 1) * 16;
    int g    = lane >> 2;
    int t4   = lane & 3;
    int row0 = blockIdx.x * 128;
    int nb0  = blockIdx.y * 64;

    float acc[4][2][4];
    #pragma unroll
    for (int mt = 0; mt < 4; mt++)
        #pragma unroll
        for (int nt = 0; nt < 2; nt++)
            #pragma unroll
            for (int j = 0; j < 4; j++) acc[mt][nt][j] = 0.f;

    auto load_tile = [&](int st, int kt) {
        #pragma unroll
        for (int i = 0; i < 4; i++) {
            int cid = tid + i * 256;
            int r = cid >> 3, c = cid & 7;
            uint32_t dst = aBase + st * 16384 + r * 128 + ((c ^ (r & 7)) << 4);
            const __half* src = A + (size_t)(row0 + r) * ldA + kt * 64 + c * 8;
            cp16p(dst, src, (row0 + r < M) ? 16u : 0u);
        }
        #pragma unroll
        for (int i = 0; i < 2; i++) {
            int cid = tid + i * 256;
            int r = cid >> 3, c = cid & 7;
            uint32_t dst = wBase + st * 8192 + r * 128 + ((c ^ (r & 7)) << 4);
            const __half* src = W + (size_t)(nb0 + r) * ldW + kt * 64 + c * 8;
            cp16(dst, src);
        }
    };

    auto compute = [&](int st) {
        uint32_t aSt = aBase + st * 16384;
        uint32_t wSt = wBase + st * 8192;
        #pragma unroll
        for (int ks = 0; ks < 4; ks++) {
            uint32_t b[2][2];
            #pragma unroll
            for (int nt = 0; nt < 2; nt++) {
                int rr = lane & 7, hh = (lane >> 3) & 1;
                int row = wn + nt * 8 + rr;
                int ch = ks * 2 + hh;
                ldsm_x2(b[nt][0], b[nt][1],
                        wSt + row * 128 + ((ch ^ (row & 7)) << 4));
            }
            #pragma unroll
            for (int mt = 0; mt < 4; mt++) {
                int q = lane >> 3, rr = lane & 7;
                int row = wm + mt * 16 + (q & 1) * 8 + rr;
                int ch = ks * 2 + (q >> 1);
                uint32_t a0, a1, a2, a3;
                ldsm_x4(a0, a1, a2, a3,
                        aSt + row * 128 + ((ch ^ (row & 7)) << 4));
                mma_f16(acc[mt][0], a0, a1, a2, a3, b[0][0], b[0][1]);
                mma_f16(acc[mt][1], a0, a1, a2, a3, b[1][0], b[1][1]);
            }
        }
    };

    load_tile(0, 0);
    cp_commit();
    #pragma unroll
    for (int t = 0; t < KTILES; t++) {
        if (t + 1 < KTILES) { load_tile((t + 1) & (STAGES - 1), t + 1); cp_commit(); }
        if (t + 1 < KTILES) cp_wait<1>(); else cp_wait<0>();
        __syncthreads();
        compute(t & (STAGES - 1));
        __syncthreads();
    }

    // ---- epilogues ----
    float bv[2][2];
    #pragma unroll
    for (int nt = 0; nt < 2; nt++) {
        int col = nb0 + wn + nt * 8 + 2 * t4;
        float2 bb = *(const float2*)&bias[col];
        bv[nt][0] = bb.x; bv[nt][1] = bb.y;
    }

    if (EPI == 0 || EPI == 2) {
        #pragma unroll
        for (int mt = 0; mt < 4; mt++) {
            int r0 = row0 + wm + mt * 16 + g;
            #pragma unroll
            for (int nt = 0; nt < 2; nt++) {
                int col = nb0 + wn + nt * 8 + 2 * t4;
                if (r0 < M) {
                    float o0 = acc[mt][nt][0] + bv[nt][0];
                    float o1 = acc[mt][nt][1] + bv[nt][1];
                    if (EPI == 2) {
                        float2 rr = *(const float2*)&residual[(size_t)r0 * ldc + col];
                        o0 += rr.x; o1 += rr.y;
                        *(float2*)&((float*)Cv)[(size_t)r0 * ldc + col] = make_float2(o0, o1);
                    } else {
                        *(__half2*)&((__half*)Cv)[(size_t)r0 * ldc + col] =
                            __floats2half2_rn(o0, o1);
                    }
                }
                int r1 = r0 + 8;
                if (r1 < M) {
                    float o2 = acc[mt][nt][2] + bv[nt][0];
                    float o3 = acc[mt][nt][3] + bv[nt][1];
                    if (EPI == 2) {
                        float2 rr = *(const float2*)&residual[(size_t)r1 * ldc + col];
                        o2 += rr.x; o3 += rr.y;
                        *(float2*)&((float*)Cv)[(size_t)r1 * ldc + col] = make_float2(o2, o3);
                    } else {
                        *(__half2*)&((__half*)Cv)[(size_t)r1 * ldc + col] =
                            __floats2half2_rn(o2, o3);
                    }
                }
            }
        }
    } else {
        // EPI 3 / 4 : staged epilogue, two rounds of 64 edges.
        #pragma unroll
        for (int r = 0; r < 2; r++) {
            // ---- stage: warps with (w&1)==r write silu values (fp32) ----
            if ((w & 1) == r) {
                #pragma unroll
                for (int mt = 0; mt < 4; mt++) {
                    int le = mt * 16 + g;                  // 0..55 (+8 below)
                    int eg = row0 + r * 64 + le;           // global edge (low)
                    float sc0 = 1.f, sc1 = 1.f;
                    if (EPI == 4) { sc0 = g_s[eg]; sc1 = g_s[eg + 8]; }
                    #pragma unroll
                    for (int nt = 0; nt < 2; nt++) {
                        int col = wn + nt * 8 + 2 * t4;
                        float d0 = silu(acc[mt][nt][0] + bv[nt][0]) * sc0;
                        float d1 = silu(acc[mt][nt][1] + bv[nt][1]) * sc0;
                        float d2 = silu(acc[mt][nt][2] + bv[nt][0]) * sc1;
                        float d3 = silu(acc[mt][nt][3] + bv[nt][1]) * sc1;
                        *(float2*)&stg[le * 68 + col]       = make_float2(d0, d1);
                        *(float2*)&stg[(le + 8) * 68 + col] = make_float2(d2, d3);
                    }
                }
            }
            __syncthreads();

            // ---- gather: 4 consecutive lanes per edge, 16B sector loads ----
            int epl = tid >> 2;           // 0..63 local edge
            int p   = tid & 3;            // 16B chunk within 64B group
            int e   = row0 + r * 64 + epl;
            int dn  = g_dst[e], sn = g_src[e];

            if (EPI == 3) {
                const uint4* qp = (const uint4*)(g_qkv_h + (size_t)dn * 768 + nb0);
                const uint4* kp = (const uint4*)(g_qkv_h + (size_t)sn * 768 + 256 + nb0);
                float part = 0.f;
                #pragma unroll
                for (int g2 = 0; g2 < 2; g2++) {
                    uint4 qu = qp[g2 * 4 + p];
                    uint4 ku = kp[g2 * 4 + p];
                    const __half2* qh = (const __half2*)&qu;
                    const __half2* kh = (const __half2*)&ku;
                    const float2* dk2 = (const float2*)&stg[epl * 68 + g2 * 32 + p * 8];
                    #pragma unroll
                    for (int j = 0; j < 4; j++) {
                        float2 qf = __half22float2(qh[j]);
                        float2 kf = __half22float2(kh[j]);
                        float2 dd = dk2[j];
                        part += dd.x * qf.x * kf.x + dd.y * qf.y * kf.y;
                    }
                }
                part += __shfl_xor_sync(0xffffffffu, part, 1);
                part += __shfl_xor_sync(0xffffffffu, part, 2);
                if (p == 0)
                    g_attn4[(size_t)blockIdx.y * E_EDGES + e] = part;
            } else { // EPI == 4
                const uint4* vp = (const uint4*)(g_qkv_h + (size_t)sn * 768 + 512 + nb0);
                float* aggp = g_agg + (size_t)dn * H + nb0;
                #pragma unroll
                for (int g2 = 0; g2 < 2; g2++) {
                    uint4 vu = vp[g2 * 4 + p];
                    const __half2* vh = (const __half2*)&vu;
                    const float2* m2 = (const float2*)&stg[epl * 68 + g2 * 32 + p * 8];
                    float o[8];
                    #pragma unroll
                    for (int j = 0; j < 4; j++) {
                        float2 vf = __half22float2(vh[j]);
                        float2 mm = m2[j];
                        o[2 * j]     = mm.x * vf.x;
                        o[2 * j + 1] = mm.y * vf.y;
                    }
                    float* dst = aggp + g2 * 32 + p * 8;
                    asm volatile("red.global.add.v4.f32 [%0], {%1, %2, %3, %4};"
                                 :: "l"(dst), "f"(o[0]), "f"(o[1]),
                                    "f"(o[2]), "f"(o[3]) : "memory");
                    asm volatile("red.global.add.v4.f32 [%0], {%1, %2, %3, %4};"
                                 :: "l"(dst + 4), "f"(o[4]), "f"(o[5]),
                                    "f"(o[6]), "f"(o[7]) : "memory");
                }
            }
            __syncthreads();
        }
    }
}

// ---------------- attn partials -> s : silu(attn) * cosine cutoff ------------
__global__ void attn_post_kernel(const float* __restrict__ ew)
{
    int e = blockIdx.x * blockDim.x + threadIdx.x;
    if (e >= E_EDGES) return;
    float a = g_attn4[e] + g_attn4[(size_t)E_EDGES + e]
            + g_attn4[(size_t)2 * E_EDGES + e] + g_attn4[(size_t)3 * E_EDGES + e];
    float r = ew[e];
    float cut = (r < 5.0f) ? 0.5f * (cosf(r * 0.62831853071795864769f) + 1.0f) : 0.0f;
    g_s[e] = a / (1.f + __expf(-a)) * cut;
}

// ---------------- launch -----------------------------------------------------
extern "C" void kernel_launch(void* const* d_in, const int* in_sizes, int n_in,
                              void* d_out, int out_size)
{
    const float* x    = (const float*)d_in[0];
    const void*  eidx = (const void*)d_in[1];
    const float* ew   = (const float*)d_in[2];
    const float* ea   = (const float*)d_in[3];
    const float* ln_g = (const float*)d_in[4];
    const float* ln_b = (const float*)d_in[5];
    const float* Wq   = (const float*)d_in[6],  *bq  = (const float*)d_in[7];
    const float* Wk   = (const float*)d_in[8],  *bk  = (const float*)d_in[9];
    const float* Wv   = (const float*)d_in[10], *bv  = (const float*)d_in[11];
    const float* Wo   = (const float*)d_in[12], *bo  = (const float*)d_in[13];
    const float* Wdk  = (const float*)d_in[14], *bdk = (const float*)d_in[15];
    const float* Wdv  = (const float*)d_in[16], *bdv = (const float*)d_in[17];
    float* out = (float*)d_out;

    __half *xnh, *qkvh, *eah, *wqkvh, *woh, *wdkh, *wdvh, *aggh;
    float *bqkv;
    cudaGetSymbolAddress((void**)&xnh,   g_xnorm_h);
    cudaGetSymbolAddress((void**)&qkvh,  g_qkv_h);
    cudaGetSymbolAddress((void**)&eah,   g_ea_h);
    cudaGetSymbolAddress((void**)&wqkvh, g_wqkv_h);
    cudaGetSymbolAddress((void**)&woh,   g_wo_h);
    cudaGetSymbolAddress((void**)&wdkh,  g_wdk_h);
    cudaGetSymbolAddress((void**)&wdvh,  g_wdv_h);
    cudaGetSymbolAddress((void**)&aggh,  g_agg_h);
    cudaGetSymbolAddress((void**)&bqkv,  g_bqkv);

    // 0. edge_index dtype detection, then fused ea-convert + idx-convert
    detect_idx_kernel<<<1, 32>>>((const int*)eidx);
    conv_ea_kernel<<<(E_EDGES * R_RBF / 8 + 255) / 256, 256>>>(ea, eidx);

    // 1. weight conversion + LayerNorm (warp-per-node)
    conv_w_kernel<<<768, 256>>>(Wq, Wk, Wv, Wo, Wdk, Wdv, bq, bk, bv);
    ln_kernel<<<N_NODES / 8, 256>>>(x, ln_g, ln_b);

    // 2. fused qkv = xn @ [Wq;Wk;Wv]^T + b  -> g_qkv_h [N][768] (half)
    dim3 gq((N_NODES + 127) / 128, 768 / 64);
    gemm_h<0, 4><<<gq, 256>>>(xnh, N_NODES, H, wqkvh, H, bqkv, qkvh, 768, nullptr);

    // 3. dk-GEMM + attention dot -> g_attn4 partials (staged gathers)
    dim3 ge(E_EDGES / 128, H / 64);
    gemm_h<3, 1><<<ge, 256>>>(eah, E_EDGES, R_RBF, wdkh, R_RBF, bdk, nullptr, 0, nullptr);

    // 4. s = silu(sum partials) * cutoff
    attn_post_kernel<<<(E_EDGES + 255) / 256, 256>>>(ew);

    // 5. dv-GEMM + message scatter -> g_agg (staged gathers, v4 REDG)
    gemm_h<4, 1><<<ge, 256>>>(eah, E_EDGES, R_RBF, wdvh, R_RBF, bdv, nullptr, 0, nullptr);

    // 6. agg fp32 -> half, then out = agg @ Wo^T + bo + x
    conv_agg_kernel<<<(N_NODES * H / 8 + 255) / 256, 256>>>();
    dim3 go((N_NODES + 127) / 128, H / 64);
    gemm_h<2, 4><<<go, 256>>>(aggh, N_NODES, H, woh, H, bo, out, H, x);
}

// round 14
// speedup vs baseline: 1.1140x; 1.1140x over previous
#include <cuda_runtime.h>
#include <cuda_fp16.h>
#include <math.h>
#include <stdint.h>

#define N_NODES 20000
#define H 256
#define R_RBF 64
#define E_EDGES 320000

// ---------------- scratch (device globals; no allocation at launch) ----------
__device__ __half g_xnorm_h[(size_t)N_NODES * H];
__device__ __half g_qkv_h[(size_t)N_NODES * 768];      // [n][q|k|v] fp16
__device__ float  g_agg[(size_t)N_NODES * H];
__device__ __half g_agg_h[(size_t)N_NODES * H];
__device__ __half g_ea_h[(size_t)E_EDGES * R_RBF];
__device__ __half g_wqkv_h[768 * H];
__device__ __half g_wo_h[H * H];
__device__ __half g_wdk_h[H * R_RBF];
__device__ __half g_wdv_h[H * R_RBF];
__device__ float  g_bqkv[768];
__device__ float  g_attn4[(size_t)4 * E_EDGES];        // per-colslice partials
__device__ float  g_s[E_EDGES];
__device__ int    g_src[E_EDGES];
__device__ int    g_dst[E_EDGES];
__device__ int    g_is64;

// ---------------- asm helpers -------------------------------------------------
__device__ __forceinline__ float silu(float t)
{
    return t / (1.f + __expf(-t));
}
__device__ __forceinline__ void mma_f16(float* d, uint32_t a0, uint32_t a1,
                                        uint32_t a2, uint32_t a3,
                                        uint32_t b0, uint32_t b1)
{
    asm volatile(
        "mma.sync.aligned.m16n8k16.row.col.f32.f16.f16.f32 "
        "{%0,%1,%2,%3},{%4,%5,%6,%7},{%8,%9},{%0,%1,%2,%3};"
        : "+f"(d[0]), "+f"(d[1]), "+f"(d[2]), "+f"(d[3])
        : "r"(a0), "r"(a1), "r"(a2), "r"(a3), "r"(b0), "r"(b1));
}
__device__ __forceinline__ void ldsm_x4(uint32_t& r0, uint32_t& r1,
                                        uint32_t& r2, uint32_t& r3, uint32_t a)
{
    asm volatile("ldmatrix.sync.aligned.m8n8.x4.shared.b16 {%0,%1,%2,%3}, [%4];"
                 : "=r"(r0), "=r"(r1), "=r"(r2), "=r"(r3) : "r"(a));
}
__device__ __forceinline__ void ldsm_x2(uint32_t& r0, uint32_t& r1, uint32_t a)
{
    asm volatile("ldmatrix.sync.aligned.m8n8.x2.shared.b16 {%0,%1}, [%2];"
                 : "=r"(r0), "=r"(r1) : "r"(a));
}
__device__ __forceinline__ void cp16(uint32_t dst, const void* src)
{
    asm volatile("cp.async.cg.shared.global [%0], [%1], 16;"
                 :: "r"(dst), "l"(src) : "memory");
}
__device__ __forceinline__ void cp16p(uint32_t dst, const void* src, uint32_t nbytes)
{
    asm volatile("cp.async.cg.shared.global [%0], [%1], 16, %2;"
                 :: "r"(dst), "l"(src), "r"(nbytes) : "memory");
}
__device__ __forceinline__ void cp_commit()
{
    asm volatile("cp.async.commit_group;" ::: "memory");
}
template<int NN>
__device__ __forceinline__ void cp_wait()
{
    asm volatile("cp.async.wait_group %0;" :: "n"(NN) : "memory");
}

// ---------------- edge_index dtype detection ---------------------------------
__global__ void detect_idx_kernel(const int* __restrict__ p)
{
    if (threadIdx.x == 0 && blockIdx.x == 0) {
        int all_zero = 1;
        for (int i = 0; i < 64; i++)
            if (p[2 * i + 1] != 0) { all_zero = 0; break; }
        g_is64 = all_zero;
    }
}

// ---------------- edge_attr fp32->fp16 + index conversion (fused) ------------
__global__ void conv_ea_kernel(const float* __restrict__ ea,
                               const void* __restrict__ p)
{
    int t = blockIdx.x * blockDim.x + threadIdx.x;
    size_t i = (size_t)t * 8;
    if (i < (size_t)E_EDGES * R_RBF) {
        float4 f0 = *(const float4*)&ea[i];
        float4 f1 = *(const float4*)&ea[i + 4];
        __half2* o = (__half2*)&g_ea_h[i];
        o[0] = __floats2half2_rn(f0.x, f0.y);
        o[1] = __floats2half2_rn(f0.z, f0.w);
        o[2] = __floats2half2_rn(f1.x, f1.y);
        o[3] = __floats2half2_rn(f1.z, f1.w);
    }
    if (t < E_EDGES) {
        if (g_is64) {
            const long long* q = (const long long*)p;
            g_src[t] = (int)q[t];
            g_dst[t] = (int)q[E_EDGES + t];
        } else {
            const int* q = (const int*)p;
            g_src[t] = q[t];
            g_dst[t] = q[E_EDGES + t];
        }
    }
}

__global__ void conv_w_kernel(const float* __restrict__ Wq, const float* __restrict__ Wk,
                              const float* __restrict__ Wv, const float* __restrict__ Wo,
                              const float* __restrict__ Wdk, const float* __restrict__ Wdv,
                              const float* __restrict__ bq, const float* __restrict__ bk,
                              const float* __restrict__ bv)
{
    int i = blockIdx.x * blockDim.x + threadIdx.x;   // 0..196607
    {   // wqkv pack
        int n = i >> 8, c = i & 255;
        float w = (n < 256) ? Wq[n * 256 + c]
                : (n < 512) ? Wk[(n - 256) * 256 + c]
                            : Wv[(n - 512) * 256 + c];
        g_wqkv_h[i] = __float2half_rn(w);
    }
    if (i < 65536) g_wo_h[i]  = __float2half_rn(Wo[i]);
    if (i < 16384) g_wdk_h[i] = __float2half_rn(Wdk[i]);
    if (i < 16384) g_wdv_h[i] = __float2half_rn(Wdv[i]);
    if (i < 768)
        g_bqkv[i] = (i < 256) ? bq[i] : (i < 512) ? bk[i - 256] : bv[i - 512];
}

__global__ void conv_agg_kernel()
{
    size_t i = ((size_t)blockIdx.x * blockDim.x + threadIdx.x) * 8;
    if (i >= (size_t)N_NODES * H) return;
    float4 f0 = *(const float4*)&g_agg[i];
    float4 f1 = *(const float4*)&g_agg[i + 4];
    __half2* o = (__half2*)&g_agg_h[i];
    o[0] = __floats2half2_rn(f0.x, f0.y);
    o[1] = __floats2half2_rn(f0.z, f0.w);
    o[2] = __floats2half2_rn(f1.x, f1.y);
    o[3] = __floats2half2_rn(f1.z, f1.w);
}

// ---------------- LayerNorm: warp per node (fp32 in -> half out, zero agg) ---
__global__ void ln_kernel(const float* __restrict__ x,
                          const float* __restrict__ g,
                          const float* __restrict__ b)
{
    int warp = threadIdx.x >> 5;
    int lane = threadIdx.x & 31;
    int n = blockIdx.x * 8 + warp;
    const float4* xr = (const float4*)(x + (size_t)n * H);
    float4 a0 = xr[lane * 2];
    float4 a1 = xr[lane * 2 + 1];
    float s1 = a0.x + a0.y + a0.z + a0.w + a1.x + a1.y + a1.z + a1.w;
    float s2 = a0.x*a0.x + a0.y*a0.y + a0.z*a0.z + a0.w*a0.w
             + a1.x*a1.x + a1.y*a1.y + a1.z*a1.z + a1.w*a1.w;
    #pragma unroll
    for (int o = 16; o; o >>= 1) {
        s1 += __shfl_xor_sync(0xffffffffu, s1, o);
        s2 += __shfl_xor_sync(0xffffffffu, s2, o);
    }
    float mu  = s1 * (1.0f / H);
    float var = s2 * (1.0f / H) - mu * mu;
    float rs  = rsqrtf(var + 1e-5f);

    float4 g0 = ((const float4*)g)[lane * 2];
    float4 g1 = ((const float4*)g)[lane * 2 + 1];
    float4 b0 = ((const float4*)b)[lane * 2];
    float4 b1 = ((const float4*)b)[lane * 2 + 1];

    __half2 h[4];
    h[0] = __floats2half2_rn((a0.x - mu) * rs * g0.x + b0.x,
                             (a0.y - mu) * rs * g0.y + b0.y);
    h[1] = __floats2half2_rn((a0.z - mu) * rs * g0.z + b0.z,
                             (a0.w - mu) * rs * g0.w + b0.w);
    h[2] = __floats2half2_rn((a1.x - mu) * rs * g1.x + b1.x,
                             (a1.y - mu) * rs * g1.y + b1.y);
    h[3] = __floats2half2_rn((a1.z - mu) * rs * g1.z + b1.z,
                             (a1.w - mu) * rs * g1.w + b1.w);
    *(uint4*)(g_xnorm_h + (size_t)n * H + lane * 8) = *(uint4*)h;

    float4 z = make_float4(0.f, 0.f, 0.f, 0.f);
    float4* ar = (float4*)(g_agg + (size_t)n * H);
    ar[lane * 2]     = z;
    ar[lane * 2 + 1] = z;
}

// ---------------- fp16 tensor-core GEMM: C = A[M,K] @ W[Nout,K]^T ------------
// Block 128x64, 8 warps (2m x 4n), warp tile 64x16, mma m16n8k16,
// cp.async, ldmatrix fragment loads. STAGES=1 when KTILES==1 (24KB smem).
// EPI 0: half C = acc + bias      (C = g_qkv_h packed, ldc=768 halfs)
// EPI 2: float C = acc + bias + residual
// EPI 3: attn partial -> g_attn4[blockIdx.y*E + e]  (no atomics, smem reduce)
// EPI 4: red.add(agg[dst], silu(acc+b) * s[e] * v[src])
template<int EPI, int KTILES>
__global__ void __launch_bounds__(256)
gemm_h(const __half* __restrict__ A, int M, int ldA,
       const __half* __restrict__ W, int ldW,
       const float* __restrict__ bias,
       void* __restrict__ Cv, int ldc,
       const float* __restrict__ residual)
{
    constexpr int STAGES = (KTILES > 1) ? 2 : 1;
    __shared__ __align__(16) __half sA[STAGES][128 * 64];
    __shared__ __align__(16) __half sW[STAGES][64 * 64];

    int tid  = threadIdx.x;
    int lane = tid & 31;
    int w    = tid >> 5;
    int wm   = (w & 1) * 64;
    int wn   = (w >> 1) * 16;
    int g    = lane >> 2;
    int t4   = lane & 3;
    int row0 = blockIdx.x * 128;
    int nb0  = blockIdx.y * 64;

    uint32_t aBase = (uint32_t)__cvta_generic_to_shared(&sA[0][0]);
    uint32_t wBase = (uint32_t)__cvta_generic_to_shared(&sW[0][0]);

    float acc[4][2][4];
    #pragma unroll
    for (int mt = 0; mt < 4; mt++)
        #pragma unroll
        for (int nt = 0; nt < 2; nt++)
            #pragma unroll
            for (int j = 0; j < 4; j++) acc[mt][nt][j] = 0.f;

    auto load_tile = [&](int st, int kt) {
        #pragma unroll
        for (int i = 0; i < 4; i++) {
            int cid = tid + i * 256;
            int r = cid >> 3, c = cid & 7;
            uint32_t dst = aBase + st * 16384 + r * 128 + ((c ^ (r & 7)) << 4);
            const __half* src = A + (size_t)(row0 + r) * ldA + kt * 64 + c * 8;
            cp16p(dst, src, (row0 + r < M) ? 16u : 0u);
        }
        #pragma unroll
        for (int i = 0; i < 2; i++) {
            int cid = tid + i * 256;
            int r = cid >> 3, c = cid & 7;
            uint32_t dst = wBase + st * 8192 + r * 128 + ((c ^ (r & 7)) << 4);
            const __half* src = W + (size_t)(nb0 + r) * ldW + kt * 64 + c * 8;
            cp16(dst, src);
        }
    };

    auto compute = [&](int st) {
        uint32_t aSt = aBase + st * 16384;
        uint32_t wSt = wBase + st * 8192;
        #pragma unroll
        for (int ks = 0; ks < 4; ks++) {
            uint32_t b[2][2];
            #pragma unroll
            for (int nt = 0; nt < 2; nt++) {
                int rr = lane & 7, hh = (lane >> 3) & 1;
                int row = wn + nt * 8 + rr;
                int ch = ks * 2 + hh;
                ldsm_x2(b[nt][0], b[nt][1],
                        wSt + row * 128 + ((ch ^ (row & 7)) << 4));
            }
            #pragma unroll
            for (int mt = 0; mt < 4; mt++) {
                int q = lane >> 3, rr = lane & 7;
                int row = wm + mt * 16 + (q & 1) * 8 + rr;
                int ch = ks * 2 + (q >> 1);
                uint32_t a0, a1, a2, a3;
                ldsm_x4(a0, a1, a2, a3,
                        aSt + row * 128 + ((ch ^ (row & 7)) << 4));
                mma_f16(acc[mt][0], a0, a1, a2, a3, b[0][0], b[0][1]);
                mma_f16(acc[mt][1], a0, a1, a2, a3, b[1][0], b[1][1]);
            }
        }
    };

    load_tile(0, 0);
    cp_commit();
    #pragma unroll
    for (int t = 0; t < KTILES; t++) {
        if (t + 1 < KTILES) { load_tile((t + 1) & (STAGES - 1), t + 1); cp_commit(); }
        if (t + 1 < KTILES) cp_wait<1>(); else cp_wait<0>();
        __syncthreads();
        compute(t & (STAGES - 1));
        __syncthreads();
    }

    // ---- epilogues ----
    float bv[2][2];
    #pragma unroll
    for (int nt = 0; nt < 2; nt++) {
        int col = nb0 + wn + nt * 8 + 2 * t4;
        float2 bb = *(const float2*)&bias[col];
        bv[nt][0] = bb.x; bv[nt][1] = bb.y;
    }

    if (EPI == 0 || EPI == 2) {
        #pragma unroll
        for (int mt = 0; mt < 4; mt++) {
            int r0 = row0 + wm + mt * 16 + g;
            #pragma unroll
            for (int nt = 0; nt < 2; nt++) {
                int col = nb0 + wn + nt * 8 + 2 * t4;
                if (r0 < M) {
                    float o0 = acc[mt][nt][0] + bv[nt][0];
                    float o1 = acc[mt][nt][1] + bv[nt][1];
                    if (EPI == 2) {
                        float2 rr = *(const float2*)&residual[(size_t)r0 * ldc + col];
                        o0 += rr.x; o1 += rr.y;
                        *(float2*)&((float*)Cv)[(size_t)r0 * ldc + col] = make_float2(o0, o1);
                    } else {
                        *(__half2*)&((__half*)Cv)[(size_t)r0 * ldc + col] =
                            __floats2half2_rn(o0, o1);
                    }
                }
                int r1 = r0 + 8;
                if (r1 < M) {
                    float o2 = acc[mt][nt][2] + bv[nt][0];
                    float o3 = acc[mt][nt][3] + bv[nt][1];
                    if (EPI == 2) {
                        float2 rr = *(const float2*)&residual[(size_t)r1 * ldc + col];
                        o2 += rr.x; o3 += rr.y;
                        *(float2*)&((float*)Cv)[(size_t)r1 * ldc + col] = make_float2(o2, o3);
                    } else {
                        *(__half2*)&((__half*)Cv)[(size_t)r1 * ldc + col] =
                            __floats2half2_rn(o2, o3);
                    }
                }
            }
        }
    } else if (EPI == 3) {
        // smem partial buffer reuses sA (mainloop done; last barrier passed)
        float (*part)[4] = (float(*)[4])&sA[0][0];
        #pragma unroll
        for (int mt = 0; mt < 4; mt++) {
            int e0 = row0 + wm + mt * 16 + g;
            int e1 = e0 + 8;
            int s0 = g_src[e0], d0 = g_dst[e0];
            int s1 = g_src[e1], d1 = g_dst[e1];
            float p0 = 0.f, p1 = 0.f;
            #pragma unroll
            for (int nt = 0; nt < 2; nt++) {
                int col = nb0 + wn + nt * 8 + 2 * t4;
                float2 q0 = __half22float2(*(const __half2*)&g_qkv_h[(size_t)d0 * 768 + col]);
                float2 k0 = __half22float2(*(const __half2*)&g_qkv_h[(size_t)s0 * 768 + 256 + col]);
                float2 q1 = __half22float2(*(const __half2*)&g_qkv_h[(size_t)d1 * 768 + col]);
                float2 k1 = __half22float2(*(const __half2*)&g_qkv_h[(size_t)s1 * 768 + 256 + col]);
                p0 += silu(acc[mt][nt][0] + bv[nt][0]) * q0.x * k0.x
                    + silu(acc[mt][nt][1] + bv[nt][1]) * q0.y * k0.y;
                p1 += silu(acc[mt][nt][2] + bv[nt][0]) * q1.x * k1.x
                    + silu(acc[mt][nt][3] + bv[nt][1]) * q1.y * k1.y;
            }
            p0 += __shfl_xor_sync(0xffffffffu, p0, 1);
            p0 += __shfl_xor_sync(0xffffffffu, p0, 2);
            p1 += __shfl_xor_sync(0xffffffffu, p1, 1);
            p1 += __shfl_xor_sync(0xffffffffu, p1, 2);
            if (t4 == 0) {
                part[wm + mt * 16 + g][w >> 1]     = p0;
                part[wm + mt * 16 + g + 8][w >> 1] = p1;
            }
        }
        __syncthreads();
        if (tid < 128) {
            float t = part[tid][0] + part[tid][1] + part[tid][2] + part[tid][3];
            g_attn4[(size_t)blockIdx.y * E_EDGES + row0 + tid] = t;
        }
    } else { // EPI == 4
        #pragma unroll
        for (int mt = 0; mt < 4; mt++) {
            int e0 = row0 + wm + mt * 16 + g;
            int e1 = e0 + 8;
            int s0 = g_src[e0], d0 = g_dst[e0];
            int s1 = g_src[e1], d1 = g_dst[e1];
            float sc0 = g_s[e0], sc1 = g_s[e1];
            #pragma unroll
            for (int nt = 0; nt < 2; nt++) {
                int col = nb0 + wn + nt * 8 + 2 * t4;
                float2 v0 = __half22float2(*(const __half2*)&g_qkv_h[(size_t)s0 * 768 + 512 + col]);
                float2 v1 = __half22float2(*(const __half2*)&g_qkv_h[(size_t)s1 * 768 + 512 + col]);
                float m00 = silu(acc[mt][nt][0] + bv[nt][0]) * sc0 * v0.x;
                float m01 = silu(acc[mt][nt][1] + bv[nt][1]) * sc0 * v0.y;
                float m10 = silu(acc[mt][nt][2] + bv[nt][0]) * sc1 * v1.x;
                float m11 = silu(acc[mt][nt][3] + bv[nt][1]) * sc1 * v1.y;
                asm volatile("red.global.add.v2.f32 [%0], {%1, %2};"
                             :: "l"(g_agg + (size_t)d0 * H + col),
                                "f"(m00), "f"(m01) : "memory");
                asm volatile("red.global.add.v2.f32 [%0], {%1, %2};"
                             :: "l"(g_agg + (size_t)d1 * H + col),
                                "f"(m10), "f"(m11) : "memory");
            }
        }
    }
}

// ---------------- attn partials -> s : silu(attn) * cosine cutoff ------------
__global__ void attn_post_kernel(const float* __restrict__ ew)
{
    int e = blockIdx.x * blockDim.x + threadIdx.x;
    if (e >= E_EDGES) return;
    float a = g_attn4[e] + g_attn4[(size_t)E_EDGES + e]
            + g_attn4[(size_t)2 * E_EDGES + e] + g_attn4[(size_t)3 * E_EDGES + e];
    float r = ew[e];
    float cut = (r < 5.0f) ? 0.5f * (cosf(r * 0.62831853071795864769f) + 1.0f) : 0.0f;
    g_s[e] = a / (1.f + __expf(-a)) * cut;
}

// ---------------- launch -----------------------------------------------------
extern "C" void kernel_launch(void* const* d_in, const int* in_sizes, int n_in,
                              void* d_out, int out_size)
{
    const float* x    = (const float*)d_in[0];
    const void*  eidx = (const void*)d_in[1];
    const float* ew   = (const float*)d_in[2];
    const float* ea   = (const float*)d_in[3];
    const float* ln_g = (const float*)d_in[4];
    const float* ln_b = (const float*)d_in[5];
    const float* Wq   = (const float*)d_in[6],  *bq  = (const float*)d_in[7];
    const float* Wk   = (const float*)d_in[8],  *bk  = (const float*)d_in[9];
    const float* Wv   = (const float*)d_in[10], *bv  = (const float*)d_in[11];
    const float* Wo   = (const float*)d_in[12], *bo  = (const float*)d_in[13];
    const float* Wdk  = (const float*)d_in[14], *bdk = (const float*)d_in[15];
    const float* Wdv  = (const float*)d_in[16], *bdv = (const float*)d_in[17];
    float* out = (float*)d_out;

    __half *xnh, *qkvh, *eah, *wqkvh, *woh, *wdkh, *wdvh, *aggh;
    float *bqkv;
    cudaGetSymbolAddress((void**)&xnh,   g_xnorm_h);
    cudaGetSymbolAddress((void**)&qkvh,  g_qkv_h);
    cudaGetSymbolAddress((void**)&eah,   g_ea_h);
    cudaGetSymbolAddress((void**)&wqkvh, g_wqkv_h);
    cudaGetSymbolAddress((void**)&woh,   g_wo_h);
    cudaGetSymbolAddress((void**)&wdkh,  g_wdk_h);
    cudaGetSymbolAddress((void**)&wdvh,  g_wdv_h);
    cudaGetSymbolAddress((void**)&aggh,  g_agg_h);
    cudaGetSymbolAddress((void**)&bqkv,  g_bqkv);

    // 0. edge_index dtype detection, then fused ea-convert + idx-convert
    detect_idx_kernel<<<1, 32>>>((const int*)eidx);
    conv_ea_kernel<<<(E_EDGES * R_RBF / 8 + 255) / 256, 256>>>(ea, eidx);

    // 1. weight conversion + LayerNorm (warp-per-node)
    conv_w_kernel<<<768, 256>>>(Wq, Wk, Wv, Wo, Wdk, Wdv, bq, bk, bv);
    ln_kernel<<<N_NODES / 8, 256>>>(x, ln_g, ln_b);

    // 2. fused qkv = xn @ [Wq;Wk;Wv]^T + b  -> g_qkv_h [N][768] (half)
    dim3 gq((N_NODES + 127) / 128, 768 / 64);
    gemm_h<0, 4><<<gq, 256>>>(xnh, N_NODES, H, wqkvh, H, bqkv, qkvh, 768, nullptr);

    // 3. dk-GEMM + attention dot -> g_attn4 partials (single-stage smem)
    dim3 ge(E_EDGES / 128, H / 64);
    gemm_h<3, 1><<<ge, 256>>>(eah, E_EDGES, R_RBF, wdkh, R_RBF, bdk, nullptr, 0, nullptr);

    // 4. s = silu(sum partials) * cutoff
    attn_post_kernel<<<(E_EDGES + 255) / 256, 256>>>(ew);

    // 5. dv-GEMM + message scatter -> g_agg (single-stage smem)
    gemm_h<4, 1><<<ge, 256>>>(eah, E_EDGES, R_RBF, wdvh, R_RBF, bdv, nullptr, 0, nullptr);

    // 6. agg fp32 -> half, then out = agg @ Wo^T + bo + x
    conv_agg_kernel<<<(N_NODES * H / 8 + 255) / 256, 256>>>();
    dim3 go((N_NODES + 127) / 128, H / 64);
    gemm_h<2, 4><<<go, 256>>>(aggh, N_NODES, H, woh, H, bo, out, H, x);
}